// round 16
// baseline (speedup 1.0000x reference)
#include <cuda_runtime.h>
#include <cuda_fp16.h>
#include <cstdint>

#define BD   8
#define SD   512
#define PD   8
#define DIN  768
#define DM   1024
#define NPOS (BD*SD)
#define EPSL 1e-5f

// ---------------- GEMM tiling (best-measured R10/R15 config) ----------------
#define BM 64
#define BN 128
#define BK 64                    // halfs (128 bytes)
#define KITERS (DIN/BK)          // 12
#define ROWB 144                 // padded row bytes
#define A_BYTES (BM*ROWB)        // 9216
#define B_BYTES (BN*ROWB)        // 18432
#define STAGE_BYTES (A_BYTES + B_BYTES)   // 27648
#define STATS_OFF   (2*STAGE_BYTES)       // 55296
#define SRED_OFF   (STATS_OFF)
#define QRED_OFF   (STATS_OFF + 512)
#define CTAS_OFF   (STATS_OFF + 1024)
#define CTAQ_OFF   (STATS_OFF + 1280)
#define MEAN_OFF   (STATS_OFF + 1536)
#define RSTD_OFF   (STATS_OFF + 1792)
#define SMEM_TOTAL (STATS_OFF + 2048)     // 57344

#define NCLUSTER 8               // DM/BN CTAs own one full row block

// Scratch
__device__ __half g_pooled[(size_t)NPOS * DIN];  // 6.3 MB
__device__ __half g_Wt[(size_t)DM * DIN];        // 1.5 MB (W^T, K-major)

__device__ __forceinline__ uint32_t smem_u32(const void* p) {
    uint32_t a;
    asm("{ .reg .u64 t; cvta.to.shared.u64 t, %1; cvt.u32.u64 %0, t; }" : "=r"(a) : "l"(p));
    return a;
}
__device__ __forceinline__ uint32_t mapa_u32(uint32_t addr, uint32_t rank) {
    uint32_t r;
    asm("mapa.shared::cluster.u32 %0, %1, %2;" : "=r"(r) : "r"(addr), "r"(rank));
    return r;
}
__device__ __forceinline__ float ld_dsm(uint32_t addr) {
    float v;
    asm volatile("ld.shared::cluster.f32 %0, [%1];" : "=f"(v) : "r"(addr));
    return v;
}
#define CLUSTER_SYNC() do { \
    asm volatile("barrier.cluster.arrive.aligned;" ::: "memory"); \
    asm volatile("barrier.cluster.wait.aligned;" ::: "memory"); } while (0)

#define CP16(dst, src) \
    asm volatile("cp.async.cg.shared.global [%0], [%1], 16;" :: "r"(dst), "l"(src))
#define CP_COMMIT() asm volatile("cp.async.commit_group;" ::: "memory")
#define CP_WAIT1()  asm volatile("cp.async.wait_group 1;" ::: "memory")
#define CP_WAIT0()  asm volatile("cp.async.wait_group 0;" ::: "memory")

#define LDSM4(r, addr) \
    asm volatile("ldmatrix.sync.aligned.m8n8.x4.shared.b16 {%0,%1,%2,%3}, [%4];" \
        : "=r"((r)[0]), "=r"((r)[1]), "=r"((r)[2]), "=r"((r)[3]) : "r"(addr))

// fp16-accumulator HMMA: D(f16) = A(f16)*B(f16) + C(f16)
__device__ __forceinline__ void mma_f16acc(uint32_t* d, const uint32_t* a,
                                           uint32_t b0, uint32_t b1) {
    asm volatile("mma.sync.aligned.m16n8k16.row.col.f16.f16.f16.f16 "
        "{%0,%1}, {%2,%3,%4,%5}, {%6,%7}, {%0,%1};"
        : "+r"(d[0]), "+r"(d[1])
        : "r"(a[0]), "r"(a[1]), "r"(a[2]), "r"(a[3]), "r"(b0), "r"(b1));
}

// ---------------------------------------------------------------------------
// Kernel 1: fused prep — blocks [0,4096): mean-pool (8-way predicated unroll);
// blocks [4096,4864): W transpose.
// ---------------------------------------------------------------------------
__global__ __launch_bounds__(256) void prep_kernel(const float* __restrict__ pv,
                                                   const int* __restrict__ np,
                                                   const float* __restrict__ W) {
    int bid = blockIdx.x;
    if (bid < NPOS) {
        if (threadIdx.x >= 192) return;
        const int n = np[bid];
        const float inv = (n > 0) ? 1.0f / (float)n : 0.0f;
        const float4* base = (const float4*)(pv + (size_t)bid * PD * DIN);
        const int c = threadIdx.x;
        float4 v[PD];
        #pragma unroll
        for (int p = 0; p < PD; ++p) {
            if (p < n) v[p] = base[p * (DIN/4) + c];
            else       v[p] = make_float4(0.f, 0.f, 0.f, 0.f);
        }
        #pragma unroll
        for (int s = 1; s < PD; s <<= 1)
            #pragma unroll
            for (int p = 0; p < PD; p += 2*s) {
                v[p].x += v[p+s].x; v[p].y += v[p+s].y;
                v[p].z += v[p+s].z; v[p].w += v[p+s].w;
            }
        __half2* o = (__half2*)(g_pooled + (size_t)bid * DIN) + c * 2;
        o[0] = __floats2half2_rn(v[0].x * inv, v[0].y * inv);
        o[1] = __floats2half2_rn(v[0].z * inv, v[0].w * inv);
    } else {
        __shared__ float t[32][33];
        int b = bid - NPOS;
        int bx = b & 31, by = b >> 5;
        int tx = threadIdx.x & 31, ty = threadIdx.x >> 5;
        #pragma unroll
        for (int i = 0; i < 32; i += 8)
            t[ty + i][tx] = W[(size_t)(by*32 + ty + i) * DM + bx*32 + tx];
        __syncthreads();
        #pragma unroll
        for (int i = 0; i < 32; i += 8)
            g_Wt[(size_t)(bx*32 + ty + i) * DIN + by*32 + tx] = __float2half_rn(t[tx][ty + i]);
    }
}

// ---------------------------------------------------------------------------
// Kernel 2: fp16 mma GEMM (fp16 acc per K-chunk, promoted to fp32 per iter)
// + fused bias + LayerNorm (8-CTA cluster along N).
// ---------------------------------------------------------------------------
__global__ __launch_bounds__(256, 3) __cluster_dims__(NCLUSTER, 1, 1)
void gemm_ln_kernel(const int* __restrict__ np,
                    const float* __restrict__ bias,
                    const float* __restrict__ gamma,
                    const float* __restrict__ beta,
                    float* __restrict__ out) {
    extern __shared__ char smem[];
    const uint32_t sb = smem_u32(smem);
    const int tid  = threadIdx.x;
    const int wid  = tid >> 5;
    const int lane = tid & 31;
    const int gID  = lane >> 2;
    const int tig  = lane & 3;
    const int wm   = wid & 3;         // m-group: 16 rows
    const int wn   = wid >> 2;        // n-group: 64 cols
    const int bm   = blockIdx.y * BM;
    const int bn   = blockIdx.x * BN;

    const int ar0 = tid >> 3, ac0 = tid & 7;
    const __half* gA = g_pooled + (size_t)(bm + ar0) * DIN + ac0 * 8;
    const __half* gB = g_Wt    + (size_t)(bn + ar0) * DIN + ac0 * 8;
    const uint32_t dA = sb + ar0 * ROWB + ac0 * 16;
    const uint32_t dB = sb + A_BYTES + ar0 * ROWB + ac0 * 16;
    #define ASTEP (32*ROWB)
    #define GSTEP (32*DIN)

    const uint32_t aoff = sb + (uint32_t)((wm*16 + (lane & 15)) * ROWB
                                          + ((lane >> 4) & 1) * 16);
    const uint32_t boff = sb + (uint32_t)A_BYTES
        + (uint32_t)((wn*64 + ((lane >> 4) & 1) * 8 + (lane & 7)) * ROWB
                     + ((lane >> 3) & 1) * 16);

    float acc[8][4];
    #pragma unroll
    for (int ni = 0; ni < 8; ni++)
        #pragma unroll
        for (int q = 0; q < 4; q++) acc[ni][q] = 0.f;

    // prologue: stage 0
    #pragma unroll
    for (int j = 0; j < 2; j++) CP16(dA + j * ASTEP, gA + (size_t)j * GSTEP);
    #pragma unroll
    for (int j = 0; j < 4; j++) CP16(dB + j * ASTEP, gB + (size_t)j * GSTEP);
    CP_COMMIT();

    #pragma unroll 1
    for (int c = 0; c < KITERS; ++c) {
        if (c + 1 < KITERS) {
            const uint32_t st = ((c + 1) & 1) * STAGE_BYTES;
            const int k0 = (c + 1) * BK;
            #pragma unroll
            for (int j = 0; j < 2; j++) CP16(dA + st + j * ASTEP, gA + (size_t)j * GSTEP + k0);
            #pragma unroll
            for (int j = 0; j < 4; j++) CP16(dB + st + j * ASTEP, gB + (size_t)j * GSTEP + k0);
            CP_COMMIT();
            CP_WAIT1();
        } else {
            CP_WAIT0();
        }
        __syncthreads();

        const uint32_t st = (c & 1) * STAGE_BYTES;

        // fp16 chunk accumulators (zeroed each K-chunk of 64)
        uint32_t acc16[8][2];
        #pragma unroll
        for (int ni = 0; ni < 8; ni++) { acc16[ni][0] = 0u; acc16[ni][1] = 0u; }

        #pragma unroll
        for (int ks = 0; ks < 4; ++ks) {
            const uint32_t kb = ks * 32;
            uint32_t af[4];
            LDSM4(af, aoff + st + kb);
            uint32_t bf[4][4];
            #pragma unroll
            for (int nip = 0; nip < 4; nip++)
                LDSM4(bf[nip], boff + st + kb + nip * 16 * ROWB);
            #pragma unroll
            for (int ni = 0; ni < 8; ni++)
                mma_f16acc(acc16[ni], af,
                           bf[ni >> 1][(ni & 1) * 2], bf[ni >> 1][(ni & 1) * 2 + 1]);
        }

        // promote chunk partials to fp32
        #pragma unroll
        for (int ni = 0; ni < 8; ni++) {
            float2 lo = __half22float2(*(__half2*)&acc16[ni][0]);
            float2 hi = __half22float2(*(__half2*)&acc16[ni][1]);
            acc[ni][0] += lo.x; acc[ni][1] += lo.y;
            acc[ni][2] += hi.x; acc[ni][3] += hi.y;
        }
        __syncthreads();
    }

    // ---------------- fused epilogue: bias + LN ----------------
    const int ncol = bn + wn * 64 + tig * 2;

    float bs[2];
    #pragma unroll
    for (int h = 0; h < 2; h++)
        bs[h] = (np[bm + wm*16 + h*8 + gID] > 0) ? 1.0f : 0.0f;

    float2 b2[8];
    #pragma unroll
    for (int ni = 0; ni < 8; ni++) b2[ni] = *(const float2*)(bias + ncol + ni * 8);

    float ps[2] = {0.f, 0.f}, pq[2] = {0.f, 0.f};
    #pragma unroll
    for (int ni = 0; ni < 8; ni++) {
        acc[ni][0] += bs[0] * b2[ni].x;
        acc[ni][1] += bs[0] * b2[ni].y;
        acc[ni][2] += bs[1] * b2[ni].x;
        acc[ni][3] += bs[1] * b2[ni].y;
        ps[0] += acc[ni][0] + acc[ni][1];
        ps[1] += acc[ni][2] + acc[ni][3];
        pq[0] += acc[ni][0]*acc[ni][0] + acc[ni][1]*acc[ni][1];
        pq[1] += acc[ni][2]*acc[ni][2] + acc[ni][3]*acc[ni][3];
    }
    #pragma unroll
    for (int o = 1; o <= 2; o <<= 1)
        #pragma unroll
        for (int i = 0; i < 2; i++) {
            ps[i] += __shfl_xor_sync(0xffffffffu, ps[i], o);
            pq[i] += __shfl_xor_sync(0xffffffffu, pq[i], o);
        }
    if (tig == 0) {
        #pragma unroll
        for (int i = 0; i < 2; i++) {
            int r = wm*16 + i*8 + gID;
            *(float*)(smem + SRED_OFF + (wn*64 + r)*4) = ps[i];
            *(float*)(smem + QRED_OFF + (wn*64 + r)*4) = pq[i];
        }
    }
    __syncthreads();
    if (tid < 64) {
        float s = *(float*)(smem + SRED_OFF + tid*4) + *(float*)(smem + SRED_OFF + (64+tid)*4);
        float q = *(float*)(smem + QRED_OFF + tid*4) + *(float*)(smem + QRED_OFF + (64+tid)*4);
        *(float*)(smem + CTAS_OFF + tid*4) = s;
        *(float*)(smem + CTAQ_OFF + tid*4) = q;
    }
    __syncthreads();
    CLUSTER_SYNC();

    if (tid < 64) {
        float s = 0.f, q = 0.f;
        #pragma unroll
        for (uint32_t rk = 0; rk < NCLUSTER; rk++) {
            s += ld_dsm(mapa_u32(sb + CTAS_OFF + tid*4, rk));
            q += ld_dsm(mapa_u32(sb + CTAQ_OFF + tid*4, rk));
        }
        float mean = s * (1.0f / DM);
        float var  = q * (1.0f / DM) - mean * mean;
        *(float*)(smem + MEAN_OFF + tid*4) = mean;
        *(float*)(smem + RSTD_OFF + tid*4) = rsqrtf(var + EPSL);
    }
    __syncthreads();

    float2 g2[8], be2[8];
    #pragma unroll
    for (int ni = 0; ni < 8; ni++) {
        g2[ni]  = *(const float2*)(gamma + ncol + ni * 8);
        be2[ni] = *(const float2*)(beta  + ncol + ni * 8);
    }
    #pragma unroll
    for (int h = 0; h < 2; h++) {
        int r = wm*16 + h*8 + gID;
        float mean = *(float*)(smem + MEAN_OFF + r*4);
        float rstd = *(float*)(smem + RSTD_OFF + r*4);
        float* prow = out + (size_t)(bm + r) * DM + ncol;
        #pragma unroll
        for (int ni = 0; ni < 8; ni++) {
            float x0 = acc[ni][h*2+0], x1 = acc[ni][h*2+1];
            float2 v = make_float2((x0 - mean) * rstd * g2[ni].x + be2[ni].x,
                                   (x1 - mean) * rstd * g2[ni].y + be2[ni].y);
            *(float2*)(prow + ni * 8) = v;
        }
    }

    CLUSTER_SYNC();   // no CTA exits while peers may still read its stats
}

// ---------------------------------------------------------------------------
extern "C" void kernel_launch(void* const* d_in, const int* in_sizes, int n_in,
                              void* d_out, int out_size) {
    const float* pv    = (const float*)d_in[0];
    const int*   np    = (const int*)d_in[1];
    const float* W     = (const float*)d_in[2];
    const float* bias  = (const float*)d_in[3];
    const float* gamma = (const float*)d_in[4];
    const float* beta  = (const float*)d_in[5];
    float* out = (float*)d_out;

    cudaFuncSetAttribute(gemm_ln_kernel,
                         cudaFuncAttributeMaxDynamicSharedMemorySize, SMEM_TOTAL);

    prep_kernel<<<NPOS + (DM/32)*(DIN/32), 256>>>(pv, np, W);
    gemm_ln_kernel<<<dim3(DM/BN, NPOS/BM), 256, SMEM_TOTAL>>>(np, bias, gamma, beta, out);
}

// round 17
// speedup vs baseline: 1.1537x; 1.1537x over previous
#include <cuda_runtime.h>
#include <cuda_fp16.h>
#include <cstdint>

#define BD   8
#define SD   512
#define PD   8
#define DIN  768
#define DM   1024
#define NPOS (BD*SD)
#define EPSL 1e-5f

// ---------------- GEMM tiling (R15 config, stats aliased into stage 0) ------
#define BM 64
#define BN 128
#define BK 64                    // halfs (128 bytes)
#define KITERS (DIN/BK)          // 12
#define ROWB 144                 // padded row bytes
#define A_BYTES (BM*ROWB)        // 9216
#define B_BYTES (BN*ROWB)        // 18432
#define STAGE_BYTES (A_BYTES + B_BYTES)   // 27648
#define SMEM_TOTAL (2*STAGE_BYTES)        // 55296  (x4 CTAs = 221184 <= 227KB)
// LN stats live in the stage-0 A region — only touched AFTER the mainloop's
// final __syncthreads (last iter reads stage 1), so no conflict.
#define SRED_OFF   0
#define QRED_OFF   512
#define CTAS_OFF   1024
#define CTAQ_OFF   1280
#define MEAN_OFF   1536
#define RSTD_OFF   1792

#define NCLUSTER 8               // DM/BN CTAs own one full row block

// Scratch
__device__ __half g_pooled[(size_t)NPOS * DIN];  // 6.3 MB
__device__ __half g_Wt[(size_t)DM * DIN];        // 1.5 MB (W^T, K-major)

__device__ __forceinline__ uint32_t smem_u32(const void* p) {
    uint32_t a;
    asm("{ .reg .u64 t; cvta.to.shared.u64 t, %1; cvt.u32.u64 %0, t; }" : "=r"(a) : "l"(p));
    return a;
}
__device__ __forceinline__ uint32_t mapa_u32(uint32_t addr, uint32_t rank) {
    uint32_t r;
    asm("mapa.shared::cluster.u32 %0, %1, %2;" : "=r"(r) : "r"(addr), "r"(rank));
    return r;
}
__device__ __forceinline__ float ld_dsm(uint32_t addr) {
    float v;
    asm volatile("ld.shared::cluster.f32 %0, [%1];" : "=f"(v) : "r"(addr));
    return v;
}
#define CLUSTER_SYNC() do { \
    asm volatile("barrier.cluster.arrive.aligned;" ::: "memory"); \
    asm volatile("barrier.cluster.wait.aligned;" ::: "memory"); } while (0)

#define CP16(dst, src) \
    asm volatile("cp.async.cg.shared.global [%0], [%1], 16;" :: "r"(dst), "l"(src))
#define CP_COMMIT() asm volatile("cp.async.commit_group;" ::: "memory")
#define CP_WAIT1()  asm volatile("cp.async.wait_group 1;" ::: "memory")
#define CP_WAIT0()  asm volatile("cp.async.wait_group 0;" ::: "memory")

#define LDSM4(r, addr) \
    asm volatile("ldmatrix.sync.aligned.m8n8.x4.shared.b16 {%0,%1,%2,%3}, [%4];" \
        : "=r"((r)[0]), "=r"((r)[1]), "=r"((r)[2]), "=r"((r)[3]) : "r"(addr))

__device__ __forceinline__ void mma_f16(float* d, const uint32_t* a,
                                        uint32_t b0, uint32_t b1) {
    asm volatile("mma.sync.aligned.m16n8k16.row.col.f32.f16.f16.f32 "
        "{%0,%1,%2,%3}, {%4,%5,%6,%7}, {%8,%9}, {%0,%1,%2,%3};"
        : "+f"(d[0]), "+f"(d[1]), "+f"(d[2]), "+f"(d[3])
        : "r"(a[0]), "r"(a[1]), "r"(a[2]), "r"(a[3]), "r"(b0), "r"(b1));
}

// ---------------------------------------------------------------------------
// Kernel 1: fused prep — blocks [0,4096): mean-pool (8-way predicated unroll,
// MLP=8); blocks [4096,4864): W transpose.
// ---------------------------------------------------------------------------
__global__ __launch_bounds__(256) void prep_kernel(const float* __restrict__ pv,
                                                   const int* __restrict__ np,
                                                   const float* __restrict__ W) {
    int bid = blockIdx.x;
    if (bid < NPOS) {
        if (threadIdx.x >= 192) return;
        const int n = np[bid];
        const float inv = (n > 0) ? 1.0f / (float)n : 0.0f;
        const float4* base = (const float4*)(pv + (size_t)bid * PD * DIN);
        const int c = threadIdx.x;
        float4 v[PD];
        #pragma unroll
        for (int p = 0; p < PD; ++p) {
            if (p < n) v[p] = base[p * (DIN/4) + c];
            else       v[p] = make_float4(0.f, 0.f, 0.f, 0.f);
        }
        #pragma unroll
        for (int s = 1; s < PD; s <<= 1)
            #pragma unroll
            for (int p = 0; p < PD; p += 2*s) {
                v[p].x += v[p+s].x; v[p].y += v[p+s].y;
                v[p].z += v[p+s].z; v[p].w += v[p+s].w;
            }
        __half2* o = (__half2*)(g_pooled + (size_t)bid * DIN) + c * 2;
        o[0] = __floats2half2_rn(v[0].x * inv, v[0].y * inv);
        o[1] = __floats2half2_rn(v[0].z * inv, v[0].w * inv);
    } else {
        __shared__ float t[32][33];
        int b = bid - NPOS;                    // 0..767
        int bx = b & 31, by = b >> 5;
        int tx = threadIdx.x & 31, ty = threadIdx.x >> 5;
        #pragma unroll
        for (int i = 0; i < 32; i += 8)
            t[ty + i][tx] = W[(size_t)(by*32 + ty + i) * DM + bx*32 + tx];
        __syncthreads();
        #pragma unroll
        for (int i = 0; i < 32; i += 8)
            g_Wt[(size_t)(bx*32 + ty + i) * DIN + by*32 + tx] = __float2half_rn(t[tx][ty + i]);
    }
}

// ---------------------------------------------------------------------------
// Kernel 2: fp16 mma GEMM + fused bias + LayerNorm (8-CTA cluster along N).
// BM=64, 8 warps of 16x64 tiles. Target 4 CTAs/SM -> single wave (512<=592).
// ---------------------------------------------------------------------------
__global__ __launch_bounds__(256, 4) __cluster_dims__(NCLUSTER, 1, 1)
void gemm_ln_kernel(const int* __restrict__ np,
                    const float* __restrict__ bias,
                    const float* __restrict__ gamma,
                    const float* __restrict__ beta,
                    float* __restrict__ out) {
    extern __shared__ char smem[];
    const uint32_t sb = smem_u32(smem);
    const int tid  = threadIdx.x;
    const int wid  = tid >> 5;
    const int lane = tid & 31;
    const int gID  = lane >> 2;
    const int tig  = lane & 3;
    const int wm   = wid & 3;         // m-group: 16 rows
    const int wn   = wid >> 2;        // n-group: 64 cols
    const int bm   = blockIdx.y * BM;
    const int bn   = blockIdx.x * BN;

    const int ar0 = tid >> 3, ac0 = tid & 7;
    const __half* gA = g_pooled + (size_t)(bm + ar0) * DIN + ac0 * 8;
    const __half* gB = g_Wt    + (size_t)(bn + ar0) * DIN + ac0 * 8;
    const uint32_t dA = sb + ar0 * ROWB + ac0 * 16;
    const uint32_t dB = sb + A_BYTES + ar0 * ROWB + ac0 * 16;
    #define ASTEP (32*ROWB)
    #define GSTEP (32*DIN)

    const uint32_t aoff = sb + (uint32_t)((wm*16 + (lane & 15)) * ROWB
                                          + ((lane >> 4) & 1) * 16);
    const uint32_t boff = sb + (uint32_t)A_BYTES
        + (uint32_t)((wn*64 + ((lane >> 4) & 1) * 8 + (lane & 7)) * ROWB
                     + ((lane >> 3) & 1) * 16);

    float acc[8][4];
    #pragma unroll
    for (int ni = 0; ni < 8; ni++)
        #pragma unroll
        for (int q = 0; q < 4; q++) acc[ni][q] = 0.f;

    // prologue: stage 0
    #pragma unroll
    for (int j = 0; j < 2; j++) CP16(dA + j * ASTEP, gA + (size_t)j * GSTEP);
    #pragma unroll
    for (int j = 0; j < 4; j++) CP16(dB + j * ASTEP, gB + (size_t)j * GSTEP);
    CP_COMMIT();

    #pragma unroll 1
    for (int c = 0; c < KITERS; ++c) {
        if (c + 1 < KITERS) {
            const uint32_t st = ((c + 1) & 1) * STAGE_BYTES;
            const int k0 = (c + 1) * BK;
            #pragma unroll
            for (int j = 0; j < 2; j++) CP16(dA + st + j * ASTEP, gA + (size_t)j * GSTEP + k0);
            #pragma unroll
            for (int j = 0; j < 4; j++) CP16(dB + st + j * ASTEP, gB + (size_t)j * GSTEP + k0);
            CP_COMMIT();
            CP_WAIT1();
        } else {
            CP_WAIT0();
        }
        __syncthreads();

        const uint32_t st = (c & 1) * STAGE_BYTES;
        #pragma unroll
        for (int ks = 0; ks < 4; ++ks) {
            const uint32_t kb = ks * 32;
            uint32_t af[4];
            LDSM4(af, aoff + st + kb);
            uint32_t bf[4][4];
            #pragma unroll
            for (int nip = 0; nip < 4; nip++)
                LDSM4(bf[nip], boff + st + kb + nip * 16 * ROWB);
            #pragma unroll
            for (int ni = 0; ni < 8; ni++)
                mma_f16(acc[ni], af,
                        bf[ni >> 1][(ni & 1) * 2], bf[ni >> 1][(ni & 1) * 2 + 1]);
        }
        __syncthreads();
    }
    // Last iter read stage 1; stage-0 region is now dead -> reuse for LN stats.

    // ---------------- fused epilogue: bias + LN ----------------
    const int ncol = bn + wn * 64 + tig * 2;

    float bs[2];
    #pragma unroll
    for (int h = 0; h < 2; h++)
        bs[h] = (np[bm + wm*16 + h*8 + gID] > 0) ? 1.0f : 0.0f;

    float2 b2[8];
    #pragma unroll
    for (int ni = 0; ni < 8; ni++) b2[ni] = *(const float2*)(bias + ncol + ni * 8);

    float ps[2] = {0.f, 0.f}, pq[2] = {0.f, 0.f};
    #pragma unroll
    for (int ni = 0; ni < 8; ni++) {
        acc[ni][0] += bs[0] * b2[ni].x;
        acc[ni][1] += bs[0] * b2[ni].y;
        acc[ni][2] += bs[1] * b2[ni].x;
        acc[ni][3] += bs[1] * b2[ni].y;
        ps[0] += acc[ni][0] + acc[ni][1];
        ps[1] += acc[ni][2] + acc[ni][3];
        pq[0] += acc[ni][0]*acc[ni][0] + acc[ni][1]*acc[ni][1];
        pq[1] += acc[ni][2]*acc[ni][2] + acc[ni][3]*acc[ni][3];
    }
    #pragma unroll
    for (int o = 1; o <= 2; o <<= 1)
        #pragma unroll
        for (int i = 0; i < 2; i++) {
            ps[i] += __shfl_xor_sync(0xffffffffu, ps[i], o);
            pq[i] += __shfl_xor_sync(0xffffffffu, pq[i], o);
        }
    if (tig == 0) {
        #pragma unroll
        for (int i = 0; i < 2; i++) {
            int r = wm*16 + i*8 + gID;
            *(float*)(smem + SRED_OFF + (wn*64 + r)*4) = ps[i];
            *(float*)(smem + QRED_OFF + (wn*64 + r)*4) = pq[i];
        }
    }
    __syncthreads();
    if (tid < 64) {
        float s = *(float*)(smem + SRED_OFF + tid*4) + *(float*)(smem + SRED_OFF + (64+tid)*4);
        float q = *(float*)(smem + QRED_OFF + tid*4) + *(float*)(smem + QRED_OFF + (64+tid)*4);
        *(float*)(smem + CTAS_OFF + tid*4) = s;
        *(float*)(smem + CTAQ_OFF + tid*4) = q;
    }
    __syncthreads();
    CLUSTER_SYNC();

    if (tid < 64) {
        float s = 0.f, q = 0.f;
        #pragma unroll
        for (uint32_t rk = 0; rk < NCLUSTER; rk++) {
            s += ld_dsm(mapa_u32(sb + CTAS_OFF + tid*4, rk));
            q += ld_dsm(mapa_u32(sb + CTAQ_OFF + tid*4, rk));
        }
        float mean = s * (1.0f / DM);
        float var  = q * (1.0f / DM) - mean * mean;
        *(float*)(smem + MEAN_OFF + tid*4) = mean;
        *(float*)(smem + RSTD_OFF + tid*4) = rsqrtf(var + EPSL);
    }
    __syncthreads();

    float2 g2[8], be2[8];
    #pragma unroll
    for (int ni = 0; ni < 8; ni++) {
        g2[ni]  = *(const float2*)(gamma + ncol + ni * 8);
        be2[ni] = *(const float2*)(beta  + ncol + ni * 8);
    }
    #pragma unroll
    for (int h = 0; h < 2; h++) {
        int r = wm*16 + h*8 + gID;
        float mean = *(float*)(smem + MEAN_OFF + r*4);
        float rstd = *(float*)(smem + RSTD_OFF + r*4);
        float* prow = out + (size_t)(bm + r) * DM + ncol;
        #pragma unroll
        for (int ni = 0; ni < 8; ni++) {
            float x0 = acc[ni][h*2+0], x1 = acc[ni][h*2+1];
            float2 v = make_float2((x0 - mean) * rstd * g2[ni].x + be2[ni].x,
                                   (x1 - mean) * rstd * g2[ni].y + be2[ni].y);
            *(float2*)(prow + ni * 8) = v;
        }
    }

    CLUSTER_SYNC();   // no CTA exits while peers may still read its stats
}

// ---------------------------------------------------------------------------
extern "C" void kernel_launch(void* const* d_in, const int* in_sizes, int n_in,
                              void* d_out, int out_size) {
    const float* pv    = (const float*)d_in[0];
    const int*   np    = (const int*)d_in[1];
    const float* W     = (const float*)d_in[2];
    const float* bias  = (const float*)d_in[3];
    const float* gamma = (const float*)d_in[4];
    const float* beta  = (const float*)d_in[5];
    float* out = (float*)d_out;

    cudaFuncSetAttribute(gemm_ln_kernel,
                         cudaFuncAttributeMaxDynamicSharedMemorySize, SMEM_TOTAL);

    prep_kernel<<<NPOS + (DM/32)*(DIN/32), 256>>>(pv, np, W);
    gemm_ln_kernel<<<dim3(DM/BN, NPOS/BM), 256, SMEM_TOTAL>>>(np, bias, gamma, beta, out);
}